// round 13
// baseline (speedup 1.0000x reference)
#include <cuda_runtime.h>
#include <cuda_bf16.h>
#include <cuda_fp8.h>
#include <cstdint>

#define NROWS 8192
#define DIM   512
#define SCALE 2.659f
#define QS    64.0f             // fp8 quantization scale
#define INVQ2 (1.0f / 4096.0f)  // 1/(QS*QS)
#define NTILES 4096             // 64 n-blocks x 64 m-blocks of 128x128

__device__ uint8_t g_img8[NROWS * DIM];
__device__ uint8_t g_txt8[NROWS * DIM];
__device__ int   g_key[NROWS];
__device__ float g_cnt[NROWS];
__device__ float g_rowsum[NROWS];
__device__ float g_rowdot[NROWS];
__device__ float g_colsum[NROWS];
__device__ float g_coldot[NROWS];
__device__ float g_csum_txt[128 * DIM];
__device__ float g_csum_img[128 * DIM];
__device__ int   g_done;

// ---------------- asm helpers ----------------
#define MMA_FP8(C, A, B0, B1)                                                \
    asm volatile(                                                            \
        "mma.sync.aligned.m16n8k32.row.col.f32.e4m3.e4m3.f32 "               \
        "{%0,%1,%2,%3}, {%4,%5,%6,%7}, {%8,%9}, {%0,%1,%2,%3};"              \
        : "+f"((C)[0]), "+f"((C)[1]), "+f"((C)[2]), "+f"((C)[3])             \
        : "r"((A)[0]), "r"((A)[1]), "r"((A)[2]), "r"((A)[3]),                \
          "r"(B0), "r"(B1))

#define LDSM4(R, ADDR)                                                       \
    asm volatile("ldmatrix.sync.aligned.m8n8.x4.shared.b16 {%0,%1,%2,%3}, [%4];" \
                 : "=r"((R)[0]), "=r"((R)[1]), "=r"((R)[2]), "=r"((R)[3])    \
                 : "r"(ADDR))

#define CP_ASYNC16(dst, src)                                                 \
    asm volatile("cp.async.cg.shared.global [%0], [%1], 16;"                 \
                 :: "r"(dst), "l"(src))
#define CP_COMMIT() asm volatile("cp.async.commit_group;" ::: "memory")
#define CP_WAIT(N)  asm volatile("cp.async.wait_group %0;" :: "n"(N) : "memory")

__device__ __forceinline__ uint32_t pack_e4m3x4(float a, float b, float c, float d) {
    uint16_t lo, hi;
    asm("cvt.rn.satfinite.e4m3x2.f32 %0, %1, %2;" : "=h"(lo) : "f"(b), "f"(a));
    asm("cvt.rn.satfinite.e4m3x2.f32 %0, %1, %2;" : "=h"(hi) : "f"(d), "f"(c));
    return (uint32_t)lo | ((uint32_t)hi << 16);
}

__device__ __forceinline__ float4 fp8x4_to_float4(uint32_t v) {
    __half2_raw lo = __nv_cvt_fp8x2_to_halfraw2((__nv_fp8x2_storage_t)(v & 0xFFFFu), __NV_E4M3);
    __half2_raw hi = __nv_cvt_fp8x2_to_halfraw2((__nv_fp8x2_storage_t)(v >> 16), __NV_E4M3);
    __half2 l = *reinterpret_cast<__half2*>(&lo);
    __half2 h = *reinterpret_cast<__half2*>(&hi);
    return make_float4(__low2float(l), __high2float(l),
                       __low2float(h), __high2float(h));
}

// ---------------------------------------------------------------------------
// Prep kernel: grid (NROWS+1, 2), 128 threads.
// ---------------------------------------------------------------------------
__global__ void prep_kernel(const float* __restrict__ text,
                            const float* __restrict__ image,
                            const int* __restrict__ p) {
    int tid = threadIdx.x;
    if (blockIdx.x == NROWS) {
        if (blockIdx.y != 0) return;
        __shared__ int viol;
        __shared__ int h[128];
        if (tid == 0) { viol = 0; g_done = 0; }
        h[tid] = 0;
        __syncthreads();
        int v = 0;
        for (int i = tid; i < NROWS / 2; i += 128) {
            int hiw = p[2 * i + 1];
            if (hiw != 0 && hiw != -1) v = 1;
        }
        if (v) atomicAdd(&viol, 1);
        __syncthreads();
        bool is64 = (viol == 0);
        for (int i = tid; i < NROWS; i += 128) {
            int l = is64 ? p[2 * i] : p[i];
            g_key[i] = (l >= 0 && l < 128) ? l : (1 << 20) + i;
            if (l >= 0 && l < 128) atomicAdd(&h[l], 1);
            g_rowsum[i] = 0.0f;
            g_colsum[i] = 0.0f;
        }
        __syncthreads();
        for (int i = tid; i < NROWS; i += 128) {
            int k = g_key[i];
            g_cnt[i] = (k < 128) ? (float)h[k] : 1.0f;
        }
        return;
    }

    int row = blockIdx.x;
    const float* src = blockIdx.y ? text : image;
    uint8_t* dst = blockIdx.y ? g_txt8 : g_img8;
    int lane = tid & 31, wid = tid >> 5;

    float4 v = ((const float4*)(src + (size_t)row * DIM))[tid];
    float ss = v.x * v.x + v.y * v.y + v.z * v.z + v.w * v.w;
#pragma unroll
    for (int o = 16; o; o >>= 1) ss += __shfl_xor_sync(0xffffffffu, ss, o);
    __shared__ float wss[4];
    if (lane == 0) wss[wid] = ss;
    __syncthreads();
    float tot = wss[0] + wss[1] + wss[2] + wss[3];
    float inv = QS / fmaxf(sqrtf(tot), 1e-12f);

    ((uint32_t*)(dst + (size_t)row * DIM))[tid] =
        pack_e4m3x4(v.x * inv, v.y * inv, v.z * inv, v.w * inv);
}

// ---------------------------------------------------------------------------
// Class-sum kernel: 256 blocks (class k = b>>1, dir = b&1), 512 threads.
// ---------------------------------------------------------------------------
__global__ void csum_kernel() {
    __shared__ float tbl[256];
    __shared__ int mlist[8192];
    __shared__ int mcnt;
    int k = blockIdx.x >> 1, dir = blockIdx.x & 1;
    const uint8_t* src = dir ? g_img8 : g_txt8;
    float* dst = dir ? g_csum_img : g_csum_txt;
    int tid = threadIdx.x;
    if (tid == 0) mcnt = 0;
    if (tid < 256) {
        __half_raw hr = __nv_cvt_fp8_to_halfraw((__nv_fp8_storage_t)tid, __NV_E4M3);
        tbl[tid] = __half2float(*reinterpret_cast<__half*>(&hr));
    }
    __syncthreads();
    for (int i = tid; i < NROWS; i += 512)
        if (g_key[i] == k) mlist[atomicAdd(&mcnt, 1)] = i;
    __syncthreads();
    int cnt = mcnt;
    float a0 = 0.f, a1 = 0.f, a2 = 0.f, a3 = 0.f;
    int m = 0;
    for (; m + 4 <= cnt; m += 4) {
        a0 += tbl[src[(size_t)mlist[m]     * DIM + tid]];
        a1 += tbl[src[(size_t)mlist[m + 1] * DIM + tid]];
        a2 += tbl[src[(size_t)mlist[m + 2] * DIM + tid]];
        a3 += tbl[src[(size_t)mlist[m + 3] * DIM + tid]];
    }
    for (; m < cnt; m++) a0 += tbl[src[(size_t)mlist[m] * DIM + tid]];
    dst[k * DIM + tid] = (a0 + a1) + (a2 + a3);
}

// ---------------------------------------------------------------------------
// Dot kernel.
// ---------------------------------------------------------------------------
__global__ void dot_kernel() {
    int tid = threadIdx.x, lane = tid & 31, w = tid >> 5;
    int base = blockIdx.x * 128 + w * 16;
    for (int rr = 0; rr < 16; rr++) {
        int row = base + rr;
        int key = g_key[row];
        const uint32_t* xa = (const uint32_t*)(g_img8 + (size_t)row * DIM) + lane * 4;
        const uint32_t* ya = (const uint32_t*)(g_txt8 + (size_t)row * DIM) + lane * 4;
        float s = 0.f, t = 0.f;
        if (key < 128) {
            const float4* Ct = (const float4*)(g_csum_txt + key * DIM) + lane * 4;
            const float4* Ci = (const float4*)(g_csum_img + key * DIM) + lane * 4;
#pragma unroll
            for (int q = 0; q < 4; q++) {
                float4 xf = fp8x4_to_float4(xa[q]);
                float4 yf = fp8x4_to_float4(ya[q]);
                float4 cf = Ct[q];
                float4 df = Ci[q];
                s += xf.x * cf.x + xf.y * cf.y + xf.z * cf.z + xf.w * cf.w;
                t += yf.x * df.x + yf.y * df.y + yf.z * df.z + yf.w * df.w;
            }
        } else {
#pragma unroll
            for (int q = 0; q < 4; q++) {
                float4 xf = fp8x4_to_float4(xa[q]);
                float4 yf = fp8x4_to_float4(ya[q]);
                s += xf.x * yf.x + xf.y * yf.y + xf.z * yf.z + xf.w * yf.w;
            }
            t = s;
        }
#pragma unroll
        for (int o = 16; o; o >>= 1) {
            s += __shfl_xor_sync(0xffffffffu, s, o);
            t += __shfl_xor_sync(0xffffffffu, t, o);
        }
        if (lane == 0) { g_rowdot[row] = s; g_coldot[row] = t; }
    }
}

// ---------------------------------------------------------------------------
// Main kernel: persistent CTAs, n-major static schedule (ti = n*64 + m).
// B (txt cols) panel RESIDENT in smem (64KB, reloaded at n-change);
// A (img rows) streamed via 3-stage cp.async ring (16KB/stage), wait(1).
// Column exp-sums accumulate in registers across m-tiles (flush at n-change);
// row exp-sums flushed per tile via cheap tig-reduction + global atomics.
// ---------------------------------------------------------------------------
__global__ __launch_bounds__(256, 2)
void unicl_gemm_kernel(float* __restrict__ out) {
    extern __shared__ char sm[];
    uint32_t sbase = (uint32_t)__cvta_generic_to_shared(sm);
    const uint32_t As_u = sbase;                // 3 stages x [128 rows][128 B]
    const uint32_t Bs_u = sbase + 49152u;       // [4 kc][128 cols][128 B]
    int*   flag_s = (int*)(sm + 114688);
    float* red_s  = (float*)(sm + 114688);      // 256 floats (reuse)

    int tid = threadIdx.x, lane = tid & 31, wid = tid >> 5;
    const uint8_t* Ag = g_img8;
    const uint8_t* Bg = g_txt8;

    // --- static schedule (n-major: ti = n*64 + m) ---
    int G = gridDim.x;
    int base = NTILES / G, rem = NTILES % G;
    int c_ = blockIdx.x;
    int ts = c_ * base + min(c_, rem);
    int cnt = base + (c_ < rem ? 1 : 0);
    int total_chunks = cnt * 4;

    // --- warp geometry: 4 m-warps (32 rows) x 2 n-warps (64 cols) ---
    int warp_m = (wid & 3) * 32;
    int warp_n = (wid >> 2) * 64;
    int g = lane >> 2, tig = lane & 3;
    uint32_t a_off = (uint32_t)(warp_m + (lane & 15)) * 128;
    uint32_t hiA = (uint32_t)(lane >> 4);
    uint32_t swA = (uint32_t)(lane & 7);
    int rB0 = warp_n + (lane & 7) + ((lane >> 4) << 3);
    uint32_t b_off = (uint32_t)rB0 * 128;
    uint32_t hiB = (uint32_t)((lane >> 3) & 1);
    uint32_t swB = (uint32_t)(lane & 7);

    const float K2q = SCALE * 1.44269504f * INVQ2;
    const float K2b = SCALE * 1.44269504f;

    auto issueA = [&](int gm0, int kc, int stage) {
        const uint8_t* asrc = Ag + (size_t)gm0 * DIM + kc * 128;
        uint32_t adst = As_u + (uint32_t)stage * 16384u;
#pragma unroll
        for (int q = 0; q < 4; q++) {
            int idx = tid + q * 256;
            int row = idx >> 3, ch = idx & 7;
            CP_ASYNC16(adst + row * 128 + ((ch ^ (row & 7)) << 4),
                       asrc + (size_t)row * DIM + ch * 16);
        }
    };

    float cse[16];
#pragma unroll
    for (int p = 0; p < 16; p++) cse[p] = 0.0f;
    int curn = -1;
    int cc = 0;
    bool need_w0 = true;

    if (cnt > 0) {
        issueA((ts & 63) << 7, 0, 0); CP_COMMIT();
        if (total_chunks > 1) {
            int n1 = ts + (1 >> 2);
            issueA((n1 & 63) << 7, 1 & 3, 1); CP_COMMIT();
        }
    }

    for (int ti = ts; ti < ts + cnt; ti++) {
        int n = ti >> 6, m = ti & 63;
        int gm0 = m << 7, n0 = n << 7;

        if (n != curn) {
            if (curn >= 0) {
                // flush column sums of the finished n-group
                int pn0 = curn << 7;
#pragma unroll
                for (int p = 0; p < 16; p++) {
                    cse[p] += __shfl_xor_sync(0xffffffffu, cse[p], 4);
                    cse[p] += __shfl_xor_sync(0xffffffffu, cse[p], 8);
                    cse[p] += __shfl_xor_sync(0xffffffffu, cse[p], 16);
                }
#pragma unroll
                for (int q = 0; q < 2; q++) {
                    int p = g * 2 + q;
                    int cidx = pn0 + warp_n + (p >> 1) * 8 + tig * 2 + (p & 1);
                    atomicAdd(&g_colsum[cidx], cse[p]);
                }
#pragma unroll
                for (int p = 0; p < 16; p++) cse[p] = 0.0f;
            }
            __syncthreads();   // all warps done reading old B
#pragma unroll
            for (int q = 0; q < 16; q++) {
                int idx = tid + q * 256;
                int kc2 = idx >> 10, col = (idx >> 3) & 127, ch = idx & 7;
                const void* src = Bg + (size_t)(n0 + col) * DIM + kc2 * 128 + ch * 16;
                uint32_t dst = Bs_u + kc2 * 16384 + col * 128 + ((ch ^ (col & 7)) << 4);
                CP_ASYNC16(dst, src);
            }
            CP_COMMIT();
            curn = n;
            need_w0 = true;
        }

        float c[2][8][4];
#pragma unroll
        for (int mf = 0; mf < 2; mf++)
#pragma unroll
            for (int nf = 0; nf < 8; nf++)
#pragma unroll
                for (int e = 0; e < 4; e++) c[mf][nf][e] = 0.0f;

#pragma unroll 1
        for (int kc = 0; kc < 4; kc++) {
            if (need_w0) { CP_WAIT(0); need_w0 = false; }
            else         { CP_WAIT(1); }
            __syncthreads();   // all warps past chunk cc-1 -> its stage reusable
            int nxt = cc + 2;
            if (nxt < total_chunks) {
                int nti = ts + (nxt >> 2);
                issueA((nti & 63) << 7, nxt & 3, nxt % 3);
                CP_COMMIT();
            }
            uint32_t Ab = As_u + (uint32_t)(cc % 3) * 16384u;
            uint32_t Bb = Bs_u + (uint32_t)kc * 16384u;
#pragma unroll
            for (int k32 = 0; k32 < 4; k32++) {
                uint32_t a0[4], a1[4], b[4][4];
                uint32_t cA = ((k32 * 2 + hiA) ^ swA) << 4;
                LDSM4(a0, Ab + a_off + cA);
                LDSM4(a1, Ab + a_off + 2048 + cA);
                uint32_t cB = ((k32 * 2 + hiB) ^ swB) << 4;
                LDSM4(b[0], Bb + b_off + cB);
                LDSM4(b[1], Bb + b_off + 2048 + cB);
                LDSM4(b[2], Bb + b_off + 4096 + cB);
                LDSM4(b[3], Bb + b_off + 6144 + cB);
#pragma unroll
                for (int j = 0; j < 4; j++) {
                    MMA_FP8(c[0][2 * j],     a0, b[j][0], b[j][1]);
                    MMA_FP8(c[0][2 * j + 1], a0, b[j][2], b[j][3]);
                    MMA_FP8(c[1][2 * j],     a1, b[j][0], b[j][1]);
                    MMA_FP8(c[1][2 * j + 1], a1, b[j][2], b[j][3]);
                }
            }
            cc++;
        }

        // --- epilogue: exp accumulation; rows flushed per tile (cheap) ---
        float rse[4] = {0.f, 0.f, 0.f, 0.f};
#pragma unroll
        for (int mf = 0; mf < 2; mf++) {
#pragma unroll
            for (int nf = 0; nf < 8; nf++) {
#pragma unroll
                for (int e = 0; e < 4; e++) {
                    float ex;
                    asm("ex2.approx.ftz.f32 %0, %1;" : "=f"(ex)
                        : "f"(fmaf(c[mf][nf][e], K2q, -K2b)));
                    rse[mf * 2 + (e >> 1)] += ex;
                    cse[nf * 2 + (e & 1)]  += ex;
                }
            }
        }
#pragma unroll
        for (int ri = 0; ri < 4; ri++) {
            float v = rse[ri];
            v += __shfl_xor_sync(0xffffffffu, v, 1);
            v += __shfl_xor_sync(0xffffffffu, v, 2);
            if (tig == 0)
                atomicAdd(&g_rowsum[gm0 + warp_m + g + ri * 8], v);
        }
    }

    if (curn >= 0) {
        int pn0 = curn << 7;
#pragma unroll
        for (int p = 0; p < 16; p++) {
            cse[p] += __shfl_xor_sync(0xffffffffu, cse[p], 4);
            cse[p] += __shfl_xor_sync(0xffffffffu, cse[p], 8);
            cse[p] += __shfl_xor_sync(0xffffffffu, cse[p], 16);
        }
#pragma unroll
        for (int q = 0; q < 2; q++) {
            int p = g * 2 + q;
            int cidx = pn0 + warp_n + (p >> 1) * 8 + tig * 2 + (p & 1);
            atomicAdd(&g_colsum[cidx], cse[p]);
        }
    }

    // --- last CTA computes the final loss ---
    __threadfence();
    __syncthreads();
    if (tid == 0) {
        int prev = atomicAdd(&g_done, 1);
        flag_s[0] = (prev == G - 1) ? 1 : 0;
    }
    __syncthreads();
    if (flag_s[0]) {
        __threadfence();
        float s = 0.0f;
        for (int i = tid; i < NROWS; i += 256) {
            float inv = (SCALE * INVQ2) / g_cnt[i];
            s += 2.0f * SCALE + logf(g_rowsum[i]) + logf(g_colsum[i])
                 - (g_rowdot[i] + g_coldot[i]) * inv;
        }
        __syncthreads();
        red_s[tid] = s;
        __syncthreads();
        for (int o = 128; o; o >>= 1) {
            if (tid < o) red_s[tid] += red_s[tid + o];
            __syncthreads();
        }
        if (tid == 0) out[0] = red_s[0] * (1.0f / (2.0f * NROWS));
    }
}

// ---------------------------------------------------------------------------
extern "C" void kernel_launch(void* const* d_in, const int* in_sizes, int n_in,
                              void* d_out, int out_size) {
    const float* text   = (const float*)d_in[0];
    const float* image  = (const float*)d_in[1];
    const int*   labels = (const int*)d_in[2];
    float* out = (float*)d_out;

    int nsm = 148;
    cudaDeviceGetAttribute(&nsm, cudaDevAttrMultiProcessorCount, 0);
    int G = 2 * nsm;

    prep_kernel<<<dim3(NROWS + 1, 2), 128>>>(text, image, labels);
    csum_kernel<<<256, 512>>>();
    dot_kernel<<<64, 256>>>();

    int smem_bytes = 114688 + 1024;
    cudaFuncSetAttribute(unicl_gemm_kernel,
                         cudaFuncAttributeMaxDynamicSharedMemorySize, smem_bytes);
    unicl_gemm_kernel<<<G, 256, smem_bytes>>>(out);
}

// round 14
// speedup vs baseline: 1.5689x; 1.5689x over previous
#include <cuda_runtime.h>
#include <cuda_bf16.h>
#include <cuda_fp8.h>
#include <cstdint>

#define NROWS 8192
#define DIM   512
#define SCALE 2.659f
#define QS    64.0f             // fp8 quantization scale
#define INVQ2 (1.0f / 4096.0f)  // 1/(QS*QS)
#define NTILES 4096             // 64 m-blocks x 64 n-blocks of 128x128

__device__ uint8_t g_img8[NROWS * DIM];
__device__ uint8_t g_txt8[NROWS * DIM];
__device__ int   g_key[NROWS];
__device__ float g_cnt[NROWS];
__device__ float g_rowsum[NROWS];
__device__ float g_rowdot[NROWS];
__device__ float g_colsum[NROWS];
__device__ float g_coldot[NROWS];
__device__ float g_csum_txt[128 * DIM];
__device__ float g_csum_img[128 * DIM];
__device__ int   g_done;

// ---------------- asm helpers ----------------
#define MMA_FP8(C, A, B0, B1)                                                \
    asm volatile(                                                            \
        "mma.sync.aligned.m16n8k32.row.col.f32.e4m3.e4m3.f32 "               \
        "{%0,%1,%2,%3}, {%4,%5,%6,%7}, {%8,%9}, {%0,%1,%2,%3};"              \
        : "+f"((C)[0]), "+f"((C)[1]), "+f"((C)[2]), "+f"((C)[3])             \
        : "r"((A)[0]), "r"((A)[1]), "r"((A)[2]), "r"((A)[3]),                \
          "r"(B0), "r"(B1))

#define LDSM4(R, ADDR)                                                       \
    asm volatile("ldmatrix.sync.aligned.m8n8.x4.shared.b16 {%0,%1,%2,%3}, [%4];" \
                 : "=r"((R)[0]), "=r"((R)[1]), "=r"((R)[2]), "=r"((R)[3])    \
                 : "r"(ADDR))

#define CP_ASYNC16(dst, src)                                                 \
    asm volatile("cp.async.cg.shared.global [%0], [%1], 16;"                 \
                 :: "r"(dst), "l"(src))
#define CP_COMMIT() asm volatile("cp.async.commit_group;" ::: "memory")
#define CP_WAIT(N)  asm volatile("cp.async.wait_group %0;" :: "n"(N) : "memory")

__device__ __forceinline__ uint32_t pack_e4m3x4(float a, float b, float c, float d) {
    uint16_t lo, hi;
    asm("cvt.rn.satfinite.e4m3x2.f32 %0, %1, %2;" : "=h"(lo) : "f"(b), "f"(a));
    asm("cvt.rn.satfinite.e4m3x2.f32 %0, %1, %2;" : "=h"(hi) : "f"(d), "f"(c));
    return (uint32_t)lo | ((uint32_t)hi << 16);
}

__device__ __forceinline__ float4 fp8x4_to_float4(uint32_t v) {
    __half2_raw lo = __nv_cvt_fp8x2_to_halfraw2((__nv_fp8x2_storage_t)(v & 0xFFFFu), __NV_E4M3);
    __half2_raw hi = __nv_cvt_fp8x2_to_halfraw2((__nv_fp8x2_storage_t)(v >> 16), __NV_E4M3);
    __half2 l = *reinterpret_cast<__half2*>(&lo);
    __half2 h = *reinterpret_cast<__half2*>(&hi);
    return make_float4(__low2float(l), __high2float(l),
                       __low2float(h), __high2float(h));
}

// ---------------------------------------------------------------------------
// Prep kernel: grid (NROWS+1, 2), 128 threads.
// ---------------------------------------------------------------------------
__global__ void prep_kernel(const float* __restrict__ text,
                            const float* __restrict__ image,
                            const int* __restrict__ p) {
    int tid = threadIdx.x;
    if (blockIdx.x == NROWS) {
        if (blockIdx.y != 0) return;
        __shared__ int viol;
        __shared__ int h[128];
        if (tid == 0) { viol = 0; g_done = 0; }
        h[tid] = 0;
        __syncthreads();
        int v = 0;
        for (int i = tid; i < NROWS / 2; i += 128) {
            int hiw = p[2 * i + 1];
            if (hiw != 0 && hiw != -1) v = 1;
        }
        if (v) atomicAdd(&viol, 1);
        __syncthreads();
        bool is64 = (viol == 0);
        for (int i = tid; i < NROWS; i += 128) {
            int l = is64 ? p[2 * i] : p[i];
            g_key[i] = (l >= 0 && l < 128) ? l : (1 << 20) + i;
            if (l >= 0 && l < 128) atomicAdd(&h[l], 1);
            g_rowsum[i] = 0.0f;
            g_colsum[i] = 0.0f;
        }
        __syncthreads();
        for (int i = tid; i < NROWS; i += 128) {
            int k = g_key[i];
            g_cnt[i] = (k < 128) ? (float)h[k] : 1.0f;
        }
        return;
    }

    int row = blockIdx.x;
    const float* src = blockIdx.y ? text : image;
    uint8_t* dst = blockIdx.y ? g_txt8 : g_img8;
    int lane = tid & 31, wid = tid >> 5;

    float4 v = ((const float4*)(src + (size_t)row * DIM))[tid];
    float ss = v.x * v.x + v.y * v.y + v.z * v.z + v.w * v.w;
#pragma unroll
    for (int o = 16; o; o >>= 1) ss += __shfl_xor_sync(0xffffffffu, ss, o);
    __shared__ float wss[4];
    if (lane == 0) wss[wid] = ss;
    __syncthreads();
    float tot = wss[0] + wss[1] + wss[2] + wss[3];
    float inv = QS / fmaxf(sqrtf(tot), 1e-12f);

    ((uint32_t*)(dst + (size_t)row * DIM))[tid] =
        pack_e4m3x4(v.x * inv, v.y * inv, v.z * inv, v.w * inv);
}

// ---------------------------------------------------------------------------
// Class-sum kernel: 256 blocks (class k = b>>1, dir = b&1), 512 threads.
// ---------------------------------------------------------------------------
__global__ void csum_kernel() {
    __shared__ float tbl[256];
    __shared__ int mlist[8192];
    __shared__ int mcnt;
    int k = blockIdx.x >> 1, dir = blockIdx.x & 1;
    const uint8_t* src = dir ? g_img8 : g_txt8;
    float* dst = dir ? g_csum_img : g_csum_txt;
    int tid = threadIdx.x;
    if (tid == 0) mcnt = 0;
    if (tid < 256) {
        __half_raw hr = __nv_cvt_fp8_to_halfraw((__nv_fp8_storage_t)tid, __NV_E4M3);
        tbl[tid] = __half2float(*reinterpret_cast<__half*>(&hr));
    }
    __syncthreads();
    for (int i = tid; i < NROWS; i += 512)
        if (g_key[i] == k) mlist[atomicAdd(&mcnt, 1)] = i;
    __syncthreads();
    int cnt = mcnt;
    float a0 = 0.f, a1 = 0.f, a2 = 0.f, a3 = 0.f;
    int m = 0;
    for (; m + 4 <= cnt; m += 4) {
        a0 += tbl[src[(size_t)mlist[m]     * DIM + tid]];
        a1 += tbl[src[(size_t)mlist[m + 1] * DIM + tid]];
        a2 += tbl[src[(size_t)mlist[m + 2] * DIM + tid]];
        a3 += tbl[src[(size_t)mlist[m + 3] * DIM + tid]];
    }
    for (; m < cnt; m++) a0 += tbl[src[(size_t)mlist[m] * DIM + tid]];
    dst[k * DIM + tid] = (a0 + a1) + (a2 + a3);
}

// ---------------------------------------------------------------------------
// Dot kernel.
// ---------------------------------------------------------------------------
__global__ void dot_kernel() {
    int tid = threadIdx.x, lane = tid & 31, w = tid >> 5;
    int base = blockIdx.x * 128 + w * 16;
    for (int rr = 0; rr < 16; rr++) {
        int row = base + rr;
        int key = g_key[row];
        const uint32_t* xa = (const uint32_t*)(g_img8 + (size_t)row * DIM) + lane * 4;
        const uint32_t* ya = (const uint32_t*)(g_txt8 + (size_t)row * DIM) + lane * 4;
        float s = 0.f, t = 0.f;
        if (key < 128) {
            const float4* Ct = (const float4*)(g_csum_txt + key * DIM) + lane * 4;
            const float4* Ci = (const float4*)(g_csum_img + key * DIM) + lane * 4;
#pragma unroll
            for (int q = 0; q < 4; q++) {
                float4 xf = fp8x4_to_float4(xa[q]);
                float4 yf = fp8x4_to_float4(ya[q]);
                float4 cf = Ct[q];
                float4 df = Ci[q];
                s += xf.x * cf.x + xf.y * cf.y + xf.z * cf.z + xf.w * cf.w;
                t += yf.x * df.x + yf.y * df.y + yf.z * df.z + yf.w * df.w;
            }
        } else {
#pragma unroll
            for (int q = 0; q < 4; q++) {
                float4 xf = fp8x4_to_float4(xa[q]);
                float4 yf = fp8x4_to_float4(ya[q]);
                s += xf.x * yf.x + xf.y * yf.y + xf.z * yf.z + xf.w * yf.w;
            }
            t = s;
        }
#pragma unroll
        for (int o = 16; o; o >>= 1) {
            s += __shfl_xor_sync(0xffffffffu, s, o);
            t += __shfl_xor_sync(0xffffffffu, t, o);
        }
        if (lane == 0) { g_rowdot[row] = s; g_coldot[row] = t; }
    }
}

// ---------------------------------------------------------------------------
// Main kernel: PERSISTENT CTAs, static contiguous tile schedule (m-major).
// grid = 2 x SMs, 256 threads (8 warps = 4m x 2n), tile 128x128.
// A panel resident (reloaded at m-change); B streamed via THREE-stage
// cp.async ring (16KB/stage), prefetch distance 2, steady-state wait(1)
// (wait(0) only on the first chunk after an A-panel reload).
// ---------------------------------------------------------------------------
__global__ __launch_bounds__(256, 2)
void unicl_gemm_kernel(float* __restrict__ out) {
    extern __shared__ char sm[];
    uint32_t sbase = (uint32_t)__cvta_generic_to_shared(sm);
    const uint32_t As_u = sbase;                // [4 kc][128 rows][128 B]
    const uint32_t Bs_u = sbase + 65536u;       // 3 stages x [128 cols][128 B]
    int*   flag_s = (int*)(sm + 114688);
    float* red_s  = (float*)(sm + 114688);      // 256 floats (reuse)

    int tid = threadIdx.x, lane = tid & 31, wid = tid >> 5;
    const uint8_t* Ag = g_img8;
    const uint8_t* Bg = g_txt8;

    // --- static schedule ---
    int G = gridDim.x;
    int base = NTILES / G, rem = NTILES % G;
    int c_ = blockIdx.x;
    int ts = c_ * base + min(c_, rem);
    int cnt = base + (c_ < rem ? 1 : 0);
    int total_chunks = cnt * 4;

    // --- warp geometry: 4 m-warps (32 rows) x 2 n-warps (64 cols) ---
    int warp_m = (wid & 3) * 32;
    int warp_n = (wid >> 2) * 64;
    int g = lane >> 2, tig = lane & 3;
    uint32_t a_off = (uint32_t)(warp_m + (lane & 15)) * 128;
    uint32_t hiA = (uint32_t)(lane >> 4);
    uint32_t swA = (uint32_t)(lane & 7);
    int rB0 = warp_n + (lane & 7) + ((lane >> 4) << 3);
    uint32_t b_off = (uint32_t)rB0 * 128;
    uint32_t hiB = (uint32_t)((lane >> 3) & 1);
    uint32_t swB = (uint32_t)(lane & 7);

    const float K2q = SCALE * 1.44269504f * INVQ2;
    const float K2b = SCALE * 1.44269504f;

    auto issueB = [&](int n0, int kc, int stage) {
        const uint8_t* bsrc = Bg + (size_t)n0 * DIM + kc * 128;
        uint32_t bdst = Bs_u + (uint32_t)stage * 16384u;
#pragma unroll
        for (int q = 0; q < 4; q++) {
            int idx = tid + q * 256;
            int row = idx >> 3, ch = idx & 7;
            CP_ASYNC16(bdst + row * 128 + ((ch ^ (row & 7)) << 4),
                       bsrc + (size_t)row * DIM + ch * 16);
        }
    };

    float rse[4] = {0.f, 0.f, 0.f, 0.f};
    int curm = -1;
    int cc = 0;
    bool need_w0 = true;

    if (total_chunks > 0) { issueB(((ts & 63) << 7), 0, 0); CP_COMMIT(); }
    if (total_chunks > 1) {
        int t1 = ts + (1 >> 2);
        issueB(((t1 & 63) << 7), 1 & 3, 1); CP_COMMIT();
    }

    for (int ti = ts; ti < ts + cnt; ti++) {
        int m = ti >> 6, n = ti & 63;
        int gm0 = m << 7, n0 = n << 7;

        if (m != curm) {
            if (curm >= 0) {
                int pg = curm << 7;
#pragma unroll
                for (int ri = 0; ri < 4; ri++) {
                    float v = rse[ri];
                    v += __shfl_xor_sync(0xffffffffu, v, 1);
                    v += __shfl_xor_sync(0xffffffffu, v, 2);
                    if (tig == 0)
                        atomicAdd(&g_rowsum[pg + warp_m + g + ri * 8], v);
                    rse[ri] = 0.0f;
                }
            }
            __syncthreads();   // all warps done reading old A
#pragma unroll
            for (int q = 0; q < 16; q++) {
                int idx = tid + q * 256;
                int kc2 = idx >> 10, row = (idx >> 3) & 127, ch = idx & 7;
                const void* src = Ag + (size_t)(gm0 + row) * DIM + kc2 * 128 + ch * 16;
                uint32_t dst = As_u + kc2 * 16384 + row * 128 + ((ch ^ (row & 7)) << 4);
                CP_ASYNC16(dst, src);
            }
            CP_COMMIT();
            curm = m;
            need_w0 = true;
        }

        float c[2][8][4];
#pragma unroll
        for (int mf = 0; mf < 2; mf++)
#pragma unroll
            for (int nf = 0; nf < 8; nf++)
#pragma unroll
                for (int e = 0; e < 4; e++) c[mf][nf][e] = 0.0f;

#pragma unroll 1
        for (int kc = 0; kc < 4; kc++) {
            if (need_w0) { CP_WAIT(0); need_w0 = false; }
            else         { CP_WAIT(1); }
            __syncthreads();   // all warps past chunk cc-1 -> its stage reusable
            int nxt = cc + 2;
            if (nxt < total_chunks) {
                int nti = ts + (nxt >> 2);
                issueB(((nti & 63) << 7), nxt & 3, nxt % 3);
                CP_COMMIT();
            }
            uint32_t Ab = As_u + kc * 16384;
            uint32_t Bb = Bs_u + (uint32_t)(cc % 3) * 16384u;
#pragma unroll
            for (int k32 = 0; k32 < 4; k32++) {
                uint32_t a0[4], a1[4], b[4][4];
                uint32_t cA = ((k32 * 2 + hiA) ^ swA) << 4;
                LDSM4(a0, Ab + a_off + cA);
                LDSM4(a1, Ab + a_off + 2048 + cA);
                uint32_t cB = ((k32 * 2 + hiB) ^ swB) << 4;
                LDSM4(b[0], Bb + b_off + cB);
                LDSM4(b[1], Bb + b_off + 2048 + cB);
                LDSM4(b[2], Bb + b_off + 4096 + cB);
                LDSM4(b[3], Bb + b_off + 6144 + cB);
#pragma unroll
                for (int j = 0; j < 4; j++) {
                    MMA_FP8(c[0][2 * j],     a0, b[j][0], b[j][1]);
                    MMA_FP8(c[0][2 * j + 1], a0, b[j][2], b[j][3]);
                    MMA_FP8(c[1][2 * j],     a1, b[j][0], b[j][1]);
                    MMA_FP8(c[1][2 * j + 1], a1, b[j][2], b[j][3]);
                }
            }
            cc++;
        }

        // --- epilogue: exp accumulation only ---
        float cse[16];
#pragma unroll
        for (int p = 0; p < 16; p++) cse[p] = 0.0f;
#pragma unroll
        for (int mf = 0; mf < 2; mf++) {
#pragma unroll
            for (int nf = 0; nf < 8; nf++) {
#pragma unroll
                for (int e = 0; e < 4; e++) {
                    float ex;
                    asm("ex2.approx.ftz.f32 %0, %1;" : "=f"(ex)
                        : "f"(fmaf(c[mf][nf][e], K2q, -K2b)));
                    rse[mf * 2 + (e >> 1)] += ex;
                    cse[nf * 2 + (e & 1)]  += ex;
                }
            }
        }
#pragma unroll
        for (int p = 0; p < 16; p++) {
            cse[p] += __shfl_xor_sync(0xffffffffu, cse[p], 4);
            cse[p] += __shfl_xor_sync(0xffffffffu, cse[p], 8);
            cse[p] += __shfl_xor_sync(0xffffffffu, cse[p], 16);
        }
#pragma unroll
        for (int q = 0; q < 2; q++) {
            int p = g * 2 + q;
            int cidx = n0 + warp_n + (p >> 1) * 8 + tig * 2 + (p & 1);
            atomicAdd(&g_colsum[cidx], cse[p]);
        }
    }

    if (curm >= 0) {
        int pg = curm << 7;
#pragma unroll
        for (int ri = 0; ri < 4; ri++) {
            float v = rse[ri];
            v += __shfl_xor_sync(0xffffffffu, v, 1);
            v += __shfl_xor_sync(0xffffffffu, v, 2);
            if (tig == 0)
                atomicAdd(&g_rowsum[pg + warp_m + g + ri * 8], v);
        }
    }

    // --- last CTA computes the final loss ---
    __threadfence();
    __syncthreads();
    if (tid == 0) {
        int prev = atomicAdd(&g_done, 1);
        flag_s[0] = (prev == G - 1) ? 1 : 0;
    }
    __syncthreads();
    if (flag_s[0]) {
        __threadfence();
        float s = 0.0f;
        for (int i = tid; i < NROWS; i += 256) {
            float inv = (SCALE * INVQ2) / g_cnt[i];
            s += 2.0f * SCALE + logf(g_rowsum[i]) + logf(g_colsum[i])
                 - (g_rowdot[i] + g_coldot[i]) * inv;
        }
        __syncthreads();
        red_s[tid] = s;
        __syncthreads();
        for (int o = 128; o; o >>= 1) {
            if (tid < o) red_s[tid] += red_s[tid + o];
            __syncthreads();
        }
        if (tid == 0) out[0] = red_s[0] * (1.0f / (2.0f * NROWS));
    }
}

// ---------------------------------------------------------------------------
extern "C" void kernel_launch(void* const* d_in, const int* in_sizes, int n_in,
                              void* d_out, int out_size) {
    const float* text   = (const float*)d_in[0];
    const float* image  = (const float*)d_in[1];
    const int*   labels = (const int*)d_in[2];
    float* out = (float*)d_out;

    int nsm = 148;
    cudaDeviceGetAttribute(&nsm, cudaDevAttrMultiProcessorCount, 0);
    int G = 2 * nsm;

    prep_kernel<<<dim3(NROWS + 1, 2), 128>>>(text, image, labels);
    csum_kernel<<<256, 512>>>();
    dot_kernel<<<64, 256>>>();

    int smem_bytes = 114688 + 1024;
    cudaFuncSetAttribute(unicl_gemm_kernel,
                         cudaFuncAttributeMaxDynamicSharedMemorySize, smem_bytes);
    unicl_gemm_kernel<<<G, 256, smem_bytes>>>(out);
}

// round 16
// speedup vs baseline: 1.5707x; 1.0011x over previous
#include <cuda_runtime.h>
#include <cuda_bf16.h>
#include <cuda_fp8.h>
#include <cstdint>

#define NROWS 8192
#define DIM   512
#define SCALE 2.659f
#define QS    64.0f             // fp8 quantization scale
#define INVQ2 (1.0f / 4096.0f)  // 1/(QS*QS)
#define NTILES 4096             // 64 m-blocks x 64 n-blocks of 128x128

__device__ uint8_t g_img8[NROWS * DIM];
__device__ uint8_t g_txt8[NROWS * DIM];
__device__ int   g_key[NROWS];
__device__ float g_cnt[NROWS];
__device__ float g_rowsum[NROWS];
__device__ float g_rowdot[NROWS];
__device__ float g_colsum[NROWS];
__device__ float g_coldot[NROWS];
__device__ float g_csum_txt[128 * DIM];
__device__ float g_csum_img[128 * DIM];
__device__ int   g_done;

// ---------------- asm helpers ----------------
#define MMA_FP8(C, A, B0, B1)                                                \
    asm volatile(                                                            \
        "mma.sync.aligned.m16n8k32.row.col.f32.e4m3.e4m3.f32 "               \
        "{%0,%1,%2,%3}, {%4,%5,%6,%7}, {%8,%9}, {%0,%1,%2,%3};"              \
        : "+f"((C)[0]), "+f"((C)[1]), "+f"((C)[2]), "+f"((C)[3])             \
        : "r"((A)[0]), "r"((A)[1]), "r"((A)[2]), "r"((A)[3]),                \
          "r"(B0), "r"(B1))

#define LDSM4(R, ADDR)                                                       \
    asm volatile("ldmatrix.sync.aligned.m8n8.x4.shared.b16 {%0,%1,%2,%3}, [%4];" \
                 : "=r"((R)[0]), "=r"((R)[1]), "=r"((R)[2]), "=r"((R)[3])    \
                 : "r"(ADDR))

#define CP_ASYNC16(dst, src)                                                 \
    asm volatile("cp.async.cg.shared.global [%0], [%1], 16;"                 \
                 :: "r"(dst), "l"(src))
#define CP_COMMIT() asm volatile("cp.async.commit_group;" ::: "memory")
#define CP_WAIT(N)  asm volatile("cp.async.wait_group %0;" :: "n"(N) : "memory")

#define HADD2(d, a, b) \
    asm("add.rn.f16x2 %0, %1, %2;" : "=r"(d) : "r"(a), "r"(b))

__device__ __forceinline__ uint32_t pack_e4m3x4(float a, float b, float c, float d) {
    uint16_t lo, hi;
    asm("cvt.rn.satfinite.e4m3x2.f32 %0, %1, %2;" : "=h"(lo) : "f"(b), "f"(a));
    asm("cvt.rn.satfinite.e4m3x2.f32 %0, %1, %2;" : "=h"(hi) : "f"(d), "f"(c));
    return (uint32_t)lo | ((uint32_t)hi << 16);
}

__device__ __forceinline__ float4 fp8x4_to_float4(uint32_t v) {
    __half2_raw lo = __nv_cvt_fp8x2_to_halfraw2((__nv_fp8x2_storage_t)(v & 0xFFFFu), __NV_E4M3);
    __half2_raw hi = __nv_cvt_fp8x2_to_halfraw2((__nv_fp8x2_storage_t)(v >> 16), __NV_E4M3);
    __half2 l = *reinterpret_cast<__half2*>(&lo);
    __half2 h = *reinterpret_cast<__half2*>(&hi);
    return make_float4(__low2float(l), __high2float(l),
                       __low2float(h), __high2float(h));
}

// ---------------------------------------------------------------------------
// Prep kernel: grid (NROWS+1, 2), 128 threads.
// ---------------------------------------------------------------------------
__global__ void prep_kernel(const float* __restrict__ text,
                            const float* __restrict__ image,
                            const int* __restrict__ p) {
    int tid = threadIdx.x;
    if (blockIdx.x == NROWS) {
        if (blockIdx.y != 0) return;
        __shared__ int viol;
        __shared__ int h[128];
        if (tid == 0) { viol = 0; g_done = 0; }
        h[tid] = 0;
        __syncthreads();
        int v = 0;
        for (int i = tid; i < NROWS / 2; i += 128) {
            int hiw = p[2 * i + 1];
            if (hiw != 0 && hiw != -1) v = 1;
        }
        if (v) atomicAdd(&viol, 1);
        __syncthreads();
        bool is64 = (viol == 0);
        for (int i = tid; i < NROWS; i += 128) {
            int l = is64 ? p[2 * i] : p[i];
            g_key[i] = (l >= 0 && l < 128) ? l : (1 << 20) + i;
            if (l >= 0 && l < 128) atomicAdd(&h[l], 1);
            g_rowsum[i] = 0.0f;
            g_colsum[i] = 0.0f;
        }
        __syncthreads();
        for (int i = tid; i < NROWS; i += 128) {
            int k = g_key[i];
            g_cnt[i] = (k < 128) ? (float)h[k] : 1.0f;
        }
        return;
    }

    int row = blockIdx.x;
    const float* src = blockIdx.y ? text : image;
    uint8_t* dst = blockIdx.y ? g_txt8 : g_img8;
    int lane = tid & 31, wid = tid >> 5;

    float4 v = ((const float4*)(src + (size_t)row * DIM))[tid];
    float ss = v.x * v.x + v.y * v.y + v.z * v.z + v.w * v.w;
#pragma unroll
    for (int o = 16; o; o >>= 1) ss += __shfl_xor_sync(0xffffffffu, ss, o);
    __shared__ float wss[4];
    if (lane == 0) wss[wid] = ss;
    __syncthreads();
    float tot = wss[0] + wss[1] + wss[2] + wss[3];
    float inv = QS / fmaxf(sqrtf(tot), 1e-12f);

    ((uint32_t*)(dst + (size_t)row * DIM))[tid] =
        pack_e4m3x4(v.x * inv, v.y * inv, v.z * inv, v.w * inv);
}

// ---------------------------------------------------------------------------
// Class-sum kernel: 256 blocks (class k = b>>1, dir = b&1), 512 threads.
// ---------------------------------------------------------------------------
__global__ void csum_kernel() {
    __shared__ float tbl[256];
    __shared__ int mlist[8192];
    __shared__ int mcnt;
    int k = blockIdx.x >> 1, dir = blockIdx.x & 1;
    const uint8_t* src = dir ? g_img8 : g_txt8;
    float* dst = dir ? g_csum_img : g_csum_txt;
    int tid = threadIdx.x;
    if (tid == 0) mcnt = 0;
    if (tid < 256) {
        __half_raw hr = __nv_cvt_fp8_to_halfraw((__nv_fp8_storage_t)tid, __NV_E4M3);
        tbl[tid] = __half2float(*reinterpret_cast<__half*>(&hr));
    }
    __syncthreads();
    for (int i = tid; i < NROWS; i += 512)
        if (g_key[i] == k) mlist[atomicAdd(&mcnt, 1)] = i;
    __syncthreads();
    int cnt = mcnt;
    float a0 = 0.f, a1 = 0.f, a2 = 0.f, a3 = 0.f;
    int m = 0;
    for (; m + 4 <= cnt; m += 4) {
        a0 += tbl[src[(size_t)mlist[m]     * DIM + tid]];
        a1 += tbl[src[(size_t)mlist[m + 1] * DIM + tid]];
        a2 += tbl[src[(size_t)mlist[m + 2] * DIM + tid]];
        a3 += tbl[src[(size_t)mlist[m + 3] * DIM + tid]];
    }
    for (; m < cnt; m++) a0 += tbl[src[(size_t)mlist[m] * DIM + tid]];
    dst[k * DIM + tid] = (a0 + a1) + (a2 + a3);
}

// ---------------------------------------------------------------------------
// Dot kernel.
// ---------------------------------------------------------------------------
__global__ void dot_kernel() {
    int tid = threadIdx.x, lane = tid & 31, w = tid >> 5;
    int base = blockIdx.x * 128 + w * 16;
    for (int rr = 0; rr < 16; rr++) {
        int row = base + rr;
        int key = g_key[row];
        const uint32_t* xa = (const uint32_t*)(g_img8 + (size_t)row * DIM) + lane * 4;
        const uint32_t* ya = (const uint32_t*)(g_txt8 + (size_t)row * DIM) + lane * 4;
        float s = 0.f, t = 0.f;
        if (key < 128) {
            const float4* Ct = (const float4*)(g_csum_txt + key * DIM) + lane * 4;
            const float4* Ci = (const float4*)(g_csum_img + key * DIM) + lane * 4;
#pragma unroll
            for (int q = 0; q < 4; q++) {
                float4 xf = fp8x4_to_float4(xa[q]);
                float4 yf = fp8x4_to_float4(ya[q]);
                float4 cf = Ct[q];
                float4 df = Ci[q];
                s += xf.x * cf.x + xf.y * cf.y + xf.z * cf.z + xf.w * cf.w;
                t += yf.x * df.x + yf.y * df.y + yf.z * df.z + yf.w * df.w;
            }
        } else {
#pragma unroll
            for (int q = 0; q < 4; q++) {
                float4 xf = fp8x4_to_float4(xa[q]);
                float4 yf = fp8x4_to_float4(ya[q]);
                s += xf.x * yf.x + xf.y * yf.y + xf.z * yf.z + xf.w * yf.w;
            }
            t = s;
        }
#pragma unroll
        for (int o = 16; o; o >>= 1) {
            s += __shfl_xor_sync(0xffffffffu, s, o);
            t += __shfl_xor_sync(0xffffffffu, t, o);
        }
        if (lane == 0) { g_rowdot[row] = s; g_coldot[row] = t; }
    }
}

// ---------------------------------------------------------------------------
// Main kernel: PERSISTENT CTAs, static contiguous tile schedule (m-major).
// Identical to R14 except the epilogue: ex2.approx.f16x2 (2 exps / MUFU op),
// packed f16x2 per-tile accumulation, packed column shuffle-reduce.
// ---------------------------------------------------------------------------
__global__ __launch_bounds__(256, 2)
void unicl_gemm_kernel(float* __restrict__ out) {
    extern __shared__ char sm[];
    uint32_t sbase = (uint32_t)__cvta_generic_to_shared(sm);
    const uint32_t As_u = sbase;                // [4 kc][128 rows][128 B]
    const uint32_t Bs_u = sbase + 65536u;       // 3 stages x [128 cols][128 B]
    int*   flag_s = (int*)(sm + 114688);
    float* red_s  = (float*)(sm + 114688);      // 256 floats (reuse)

    int tid = threadIdx.x, lane = tid & 31, wid = tid >> 5;
    const uint8_t* Ag = g_img8;
    const uint8_t* Bg = g_txt8;

    // --- static schedule ---
    int G = gridDim.x;
    int base = NTILES / G, rem = NTILES % G;
    int c_ = blockIdx.x;
    int ts = c_ * base + min(c_, rem);
    int cnt = base + (c_ < rem ? 1 : 0);
    int total_chunks = cnt * 4;

    // --- warp geometry: 4 m-warps (32 rows) x 2 n-warps (64 cols) ---
    int warp_m = (wid & 3) * 32;
    int warp_n = (wid >> 2) * 64;
    int g = lane >> 2, tig = lane & 3;
    uint32_t a_off = (uint32_t)(warp_m + (lane & 15)) * 128;
    uint32_t hiA = (uint32_t)(lane >> 4);
    uint32_t swA = (uint32_t)(lane & 7);
    int rB0 = warp_n + (lane & 7) + ((lane >> 4) << 3);
    uint32_t b_off = (uint32_t)rB0 * 128;
    uint32_t hiB = (uint32_t)((lane >> 3) & 1);
    uint32_t swB = (uint32_t)(lane & 7);

    const float K2q = SCALE * 1.44269504f * INVQ2;
    const float K2b = SCALE * 1.44269504f;

    auto issueB = [&](int n0, int kc, int stage) {
        const uint8_t* bsrc = Bg + (size_t)n0 * DIM + kc * 128;
        uint32_t bdst = Bs_u + (uint32_t)stage * 16384u;
#pragma unroll
        for (int q = 0; q < 4; q++) {
            int idx = tid + q * 256;
            int row = idx >> 3, ch = idx & 7;
            CP_ASYNC16(bdst + row * 128 + ((ch ^ (row & 7)) << 4),
                       bsrc + (size_t)row * DIM + ch * 16);
        }
    };

    float rse[4] = {0.f, 0.f, 0.f, 0.f};
    int curm = -1;
    int cc = 0;
    bool need_w0 = true;

    if (total_chunks > 0) { issueB(((ts & 63) << 7), 0, 0); CP_COMMIT(); }
    if (total_chunks > 1) {
        int t1 = ts + (1 >> 2);
        issueB(((t1 & 63) << 7), 1 & 3, 1); CP_COMMIT();
    }

    for (int ti = ts; ti < ts + cnt; ti++) {
        int m = ti >> 6, n = ti & 63;
        int gm0 = m << 7, n0 = n << 7;

        if (m != curm) {
            if (curm >= 0) {
                int pg = curm << 7;
#pragma unroll
                for (int ri = 0; ri < 4; ri++) {
                    float v = rse[ri];
                    v += __shfl_xor_sync(0xffffffffu, v, 1);
                    v += __shfl_xor_sync(0xffffffffu, v, 2);
                    if (tig == 0)
                        atomicAdd(&g_rowsum[pg + warp_m + g + ri * 8], v);
                    rse[ri] = 0.0f;
                }
            }
            __syncthreads();   // all warps done reading old A
#pragma unroll
            for (int q = 0; q < 16; q++) {
                int idx = tid + q * 256;
                int kc2 = idx >> 10, row = (idx >> 3) & 127, ch = idx & 7;
                const void* src = Ag + (size_t)(gm0 + row) * DIM + kc2 * 128 + ch * 16;
                uint32_t dst = As_u + kc2 * 16384 + row * 128 + ((ch ^ (row & 7)) << 4);
                CP_ASYNC16(dst, src);
            }
            CP_COMMIT();
            curm = m;
            need_w0 = true;
        }

        float c[2][8][4];
#pragma unroll
        for (int mf = 0; mf < 2; mf++)
#pragma unroll
            for (int nf = 0; nf < 8; nf++)
#pragma unroll
                for (int e = 0; e < 4; e++) c[mf][nf][e] = 0.0f;

#pragma unroll 1
        for (int kc = 0; kc < 4; kc++) {
            if (need_w0) { CP_WAIT(0); need_w0 = false; }
            else         { CP_WAIT(1); }
            __syncthreads();   // all warps past chunk cc-1 -> its stage reusable
            int nxt = cc + 2;
            if (nxt < total_chunks) {
                int nti = ts + (nxt >> 2);
                issueB(((nti & 63) << 7), nxt & 3, nxt % 3);
                CP_COMMIT();
            }
            uint32_t Ab = As_u + kc * 16384;
            uint32_t Bb = Bs_u + (uint32_t)(cc % 3) * 16384u;
#pragma unroll
            for (int k32 = 0; k32 < 4; k32++) {
                uint32_t a0[4], a1[4], b[4][4];
                uint32_t cA = ((k32 * 2 + hiA) ^ swA) << 4;
                LDSM4(a0, Ab + a_off + cA);
                LDSM4(a1, Ab + a_off + 2048 + cA);
                uint32_t cB = ((k32 * 2 + hiB) ^ swB) << 4;
                LDSM4(b[0], Bb + b_off + cB);
                LDSM4(b[1], Bb + b_off + 2048 + cB);
                LDSM4(b[2], Bb + b_off + 4096 + cB);
                LDSM4(b[3], Bb + b_off + 6144 + cB);
#pragma unroll
                for (int j = 0; j < 4; j++) {
                    MMA_FP8(c[0][2 * j],     a0, b[j][0], b[j][1]);
                    MMA_FP8(c[0][2 * j + 1], a0, b[j][2], b[j][3]);
                    MMA_FP8(c[1][2 * j],     a1, b[j][0], b[j][1]);
                    MMA_FP8(c[1][2 * j + 1], a1, b[j][2], b[j][3]);
                }
            }
            cc++;
        }

        // --- epilogue: f16x2 exp (2 exps per MUFU op), packed accumulation ---
        uint32_t rse2[4], cse2[8];
#pragma unroll
        for (int i = 0; i < 4; i++) rse2[i] = 0;
#pragma unroll
        for (int i = 0; i < 8; i++) cse2[i] = 0;
#pragma unroll
        for (int mf = 0; mf < 2; mf++) {
#pragma unroll
            for (int nf = 0; nf < 8; nf++) {
                float a0 = fmaf(c[mf][nf][0], K2q, -K2b);
                float a1 = fmaf(c[mf][nf][1], K2q, -K2b);
                float a2 = fmaf(c[mf][nf][2], K2q, -K2b);
                float a3 = fmaf(c[mf][nf][3], K2q, -K2b);
                uint32_t p01, p23, x01, x23, s;
                asm("cvt.rn.f16x2.f32 %0, %1, %2;" : "=r"(p01) : "f"(a1), "f"(a0));
                asm("cvt.rn.f16x2.f32 %0, %1, %2;" : "=r"(p23) : "f"(a3), "f"(a2));
                asm("ex2.approx.f16x2 %0, %1;" : "=r"(x01) : "r"(p01));
                asm("ex2.approx.f16x2 %0, %1;" : "=r"(x23) : "r"(p23));
                HADD2(rse2[mf * 2],     rse2[mf * 2],     x01);
                HADD2(rse2[mf * 2 + 1], rse2[mf * 2 + 1], x23);
                HADD2(s, x01, x23);
                HADD2(cse2[nf], cse2[nf], s);
            }
        }
        // fold rows (h0+h1) into persistent f32 accumulators
#pragma unroll
        for (int ri = 0; ri < 4; ri++) {
            uint32_t sw, tot;
            asm("prmt.b32 %0, %1, %1, 0x1032;" : "=r"(sw) : "r"(rse2[ri]));
            HADD2(tot, rse2[ri], sw);
            float f;
            asm("{ .reg .b16 lo, hi; mov.b32 {lo, hi}, %1; cvt.f32.f16 %0, lo; }"
                : "=f"(f) : "r"(tot));
            rse[ri] += f;
        }
        // packed column pair reduce over row-groups (g), then flush
        uint32_t mypair = 0;
#pragma unroll
        for (int p8 = 0; p8 < 8; p8++) {
            uint32_t v = cse2[p8], t;
            t = __shfl_xor_sync(0xffffffffu, v, 4);  HADD2(v, v, t);
            t = __shfl_xor_sync(0xffffffffu, v, 8);  HADD2(v, v, t);
            t = __shfl_xor_sync(0xffffffffu, v, 16); HADD2(v, v, t);
            if (g == p8) mypair = v;
        }
        {
            float f0, f1;
            asm("{ .reg .b16 lo, hi; mov.b32 {lo, hi}, %2;"
                " cvt.f32.f16 %0, lo; cvt.f32.f16 %1, hi; }"
                : "=f"(f0), "=f"(f1) : "r"(mypair));
            int cidx = n0 + warp_n + g * 8 + tig * 2;
            atomicAdd(&g_colsum[cidx],     f0);
            atomicAdd(&g_colsum[cidx + 1], f1);
        }
    }

    if (curm >= 0) {
        int pg = curm << 7;
#pragma unroll
        for (int ri = 0; ri < 4; ri++) {
            float v = rse[ri];
            v += __shfl_xor_sync(0xffffffffu, v, 1);
            v += __shfl_xor_sync(0xffffffffu, v, 2);
            if (tig == 0)
                atomicAdd(&g_rowsum[pg + warp_m + g + ri * 8], v);
        }
    }

    // --- last CTA computes the final loss ---
    __threadfence();
    __syncthreads();
    if (tid == 0) {
        int prev = atomicAdd(&g_done, 1);
        flag_s[0] = (prev == G - 1) ? 1 : 0;
    }
    __syncthreads();
    if (flag_s[0]) {
        __threadfence();
        float s = 0.0f;
        for (int i = tid; i < NROWS; i += 256) {
            float inv = (SCALE * INVQ2) / g_cnt[i];
            s += 2.0f * SCALE + logf(g_rowsum[i]) + logf(g_colsum[i])
                 - (g_rowdot[i] + g_coldot[i]) * inv;
        }
        __syncthreads();
        red_s[tid] = s;
        __syncthreads();
        for (int o = 128; o; o >>= 1) {
            if (tid < o) red_s[tid] += red_s[tid + o];
            __syncthreads();
        }
        if (tid == 0) out[0] = red_s[0] * (1.0f / (2.0f * NROWS));
    }
}

// ---------------------------------------------------------------------------
extern "C" void kernel_launch(void* const* d_in, const int* in_sizes, int n_in,
                              void* d_out, int out_size) {
    const float* text   = (const float*)d_in[0];
    const float* image  = (const float*)d_in[1];
    const int*   labels = (const int*)d_in[2];
    float* out = (float*)d_out;

    int nsm = 148;
    cudaDeviceGetAttribute(&nsm, cudaDevAttrMultiProcessorCount, 0);
    int G = 2 * nsm;

    prep_kernel<<<dim3(NROWS + 1, 2), 128>>>(text, image, labels);
    csum_kernel<<<256, 512>>>();
    dot_kernel<<<64, 256>>>();

    int smem_bytes = 114688 + 1024;
    cudaFuncSetAttribute(unicl_gemm_kernel,
                         cudaFuncAttributeMaxDynamicSharedMemorySize, smem_bytes);
    unicl_gemm_kernel<<<G, 256, smem_bytes>>>(out);
}